// round 15
// baseline (speedup 1.0000x reference)
#include <cuda_runtime.h>
#include <cuda_bf16.h>
#include <math.h>

// Problem dims
#define SEQ    512
#define BATCH  128
#define INDIM  256
#define HID    512
#define ODIM   128
#define BH     (BATCH * HID)

// Recurrence: 16 batch groups of 8 rows; 16 hidden slices of 32 cols.
// 128 CTAs; CTA (q,c) runs TWO interleaved chains: group q (A), q+8 (B).
#define NG     16                   // batch groups (8 rows each)
#define BGR    8                    // rows per group
#define NCR    32                   // cols per slice (= lanes)
#define KCH    32                   // k per warp (16 warps x 32 = 512)
#define NPROD  128                  // producers per group flag: 16 CTAs x 8 warps
#define FST    544                  // per-group flag stride (ints)

__device__ float g_buf[(size_t)SEQ * BATCH * HID];
__device__ int g_flags[NG * FST];

typedef unsigned long long ull;

__device__ __forceinline__ ull fma2(ull a, ull b, ull c) {
    ull d;
    asm("fma.rn.f32x2 %0, %1, %2, %3;" : "=l"(d) : "l"(a), "l"(b), "l"(c));
    return d;
}
__device__ __forceinline__ void upk(ull v, float& x, float& y) {
    asm("mov.b64 {%0,%1}, %2;" : "=f"(x), "=f"(y) : "l"(v));
}
__device__ __forceinline__ ull pk(float x, float y) {
    ull d;
    asm("mov.b64 %0, {%1,%2};" : "=l"(d) : "f"(x), "f"(y));
    return d;
}
__device__ __forceinline__ ull dup2(float v) {
    ull d;
    asm("mov.b64 %0, {%1,%1};" : "=l"(d) : "f"(v));
    return d;
}
__device__ __forceinline__ int ldacq(const int* p) {
    int v;
    asm volatile("ld.acquire.gpu.b32 %0, [%1];" : "=r"(v) : "l"(p));
    return v;
}
__device__ __forceinline__ void red_release(int* p, int v) {
    asm volatile("red.release.gpu.global.add.s32 [%0], %1;" :: "l"(p), "r"(v)
                 : "memory");
}

// ---------------------------------------------------------------------------
__global__ void zero_flags_kernel() {
    int i = blockIdx.x * blockDim.x + threadIdx.x;
    if (i < NG * FST) g_flags[i] = 0;
}

// ---------------------------------------------------------------------------
// Tiled fp32 GEMM with bias: C[M,N] = A[M,K] @ B[K,N] + bias[N]
// BM=128, BN=64, BK=16, TM=8, TN=4.  Inner loop packs accumulators along M
// (sA is stored transposed, so M-pairs are contiguous) and uses fma.rn.f32x2:
// per BK-step 3x LDS.128 + 4 dup movs + 16 FFMA2 (was 12 LDS + 32 FFMA).
// Same products, same per-element accumulation order -> bit-identical.
// ---------------------------------------------------------------------------
template <int BM, int BN, int BK, int TM, int TN>
__global__ void __launch_bounds__(256, 2)
sgemm_bias_kernel(const float* __restrict__ A,
                  const float* __restrict__ B,
                  const float* __restrict__ bias,
                  float* __restrict__ C,
                  int M, int N, int K) {
    static_assert(TM == 8 && TN == 4, "packed path assumes TM=8, TN=4");
    __shared__ float sA[BK][BM + 4];   // transposed: [k][m]
    __shared__ float sB[BK][BN];

    const int tid = threadIdx.x;
    const int tx = tid % (BN / TN);
    const int ty = tid / (BN / TN);
    const int m0 = blockIdx.y * BM;
    const int n0 = blockIdx.x * BN;

    // acc2[p][j]: packed pair (rows 2p, 2p+1) x col j
    ull acc2[TM / 2][TN];
#pragma unroll
    for (int p = 0; p < TM / 2; p++)
#pragma unroll
        for (int j = 0; j < TN; j++) acc2[p][j] = 0;

    for (int k0 = 0; k0 < K; k0 += BK) {
#pragma unroll
        for (int i = 0; i < (BM * BK) / (256 * 4); ++i) {
            int idx = tid + i * 256;
            int r   = idx / (BK / 4);
            int kq  = (idx % (BK / 4)) * 4;
            float4 v = *(const float4*)&A[(size_t)(m0 + r) * K + k0 + kq];
            sA[kq + 0][r] = v.x;
            sA[kq + 1][r] = v.y;
            sA[kq + 2][r] = v.z;
            sA[kq + 3][r] = v.w;
        }
#pragma unroll
        for (int i = 0; i < (BK * BN) / (256 * 4); ++i) {
            int idx = tid + i * 256;
            int r   = idx / (BN / 4);
            int cq  = (idx % (BN / 4)) * 4;
            *(float4*)&sB[r][cq] =
                *(const float4*)&B[(size_t)(k0 + r) * N + n0 + cq];
        }
        __syncthreads();

#pragma unroll
        for (int kk = 0; kk < BK; ++kk) {
            // 8 M-values = 4 packed pairs (contiguous in transposed sA).
            ulonglong2 ra01 = *(const ulonglong2*)&sA[kk][ty * TM];
            ulonglong2 ra23 = *(const ulonglong2*)&sA[kk][ty * TM + 4];
            float4 bv = *(const float4*)&sB[kk][tx * TN];
            ull rb0 = dup2(bv.x), rb1 = dup2(bv.y);
            ull rb2 = dup2(bv.z), rb3 = dup2(bv.w);

            acc2[0][0] = fma2(ra01.x, rb0, acc2[0][0]);
            acc2[0][1] = fma2(ra01.x, rb1, acc2[0][1]);
            acc2[0][2] = fma2(ra01.x, rb2, acc2[0][2]);
            acc2[0][3] = fma2(ra01.x, rb3, acc2[0][3]);
            acc2[1][0] = fma2(ra01.y, rb0, acc2[1][0]);
            acc2[1][1] = fma2(ra01.y, rb1, acc2[1][1]);
            acc2[1][2] = fma2(ra01.y, rb2, acc2[1][2]);
            acc2[1][3] = fma2(ra01.y, rb3, acc2[1][3]);
            acc2[2][0] = fma2(ra23.x, rb0, acc2[2][0]);
            acc2[2][1] = fma2(ra23.x, rb1, acc2[2][1]);
            acc2[2][2] = fma2(ra23.x, rb2, acc2[2][2]);
            acc2[2][3] = fma2(ra23.x, rb3, acc2[2][3]);
            acc2[3][0] = fma2(ra23.y, rb0, acc2[3][0]);
            acc2[3][1] = fma2(ra23.y, rb1, acc2[3][1]);
            acc2[3][2] = fma2(ra23.y, rb2, acc2[3][2]);
            acc2[3][3] = fma2(ra23.y, rb3, acc2[3][3]);
        }
        __syncthreads();
    }

#pragma unroll
    for (int p = 0; p < TM / 2; p++) {
        int rowE = m0 + ty * TM + 2 * p;
#pragma unroll
        for (int j = 0; j < TN; j++) {
            int col = n0 + tx * TN + j;
            float lo, hi;
            upk(acc2[p][j], lo, hi);
            C[(size_t)rowE * N + col]       = lo + bias[col];
            C[(size_t)(rowE + 1) * N + col] = hi + bias[col];
        }
    }
}

// ---------------------------------------------------------------------------
// Persistent recurrence, two interleaved chains, per-warp stage & publish,
// cross-phase stage prefetch hoisted to post-dot (R13-proven, UNCHANGED).
// ---------------------------------------------------------------------------
#define SHT_W   256                           // floats per warp region
#define SRD_SZ  (BGR * 16 * NCR)              // 4096 floats
#define REC_SMEM_BYTES ((2 * 16 * SHT_W + 2 * SRD_SZ) * 4)   // 64 KB

__global__ void __launch_bounds__(512, 1)
rnn_recur_kernel(const float* __restrict__ Whh) {
    extern __shared__ float sm[];
    float* sHtA = sm;                          // [16 w][256]
    float* sHtB = sm + 16 * SHT_W;
    float* sRdA = sm + 2 * 16 * SHT_W;         // [8 r][16 ww][32 j]
    float* sRdB = sRdA + SRD_SZ;

    const int tid = threadIdx.x;
    const int w = tid >> 5;               // warp = k-chunk id (row id if w<8)
    const int j = tid & 31;               // lane = column
    const int q = blockIdx.x >> 4;        // pair slot 0..7
    const int c = blockIdx.x & 15;        // slice 0..15
    const int cb = c * NCR;
    const int rbA = q * BGR, rbB = (q + 8) * BGR;
    const int K0 = w * KCH;

    ull wp[KCH / 2];
#pragma unroll
    for (int p = 0; p < KCH / 2; ++p) {
        float lo = Whh[(size_t)(K0 + 2 * p)     * HID + cb + j];
        float hi = Whh[(size_t)(K0 + 2 * p + 1) * HID + cb + j];
        wp[p] = pk(lo, hi);
    }

    const int r0 = j >> 3, s0 = j & 7;         // idx j   : rows 0..3
    const int r1 = r0 + 4, s1 = s0;            // idx j+32: rows 4..7
    float* const sWA = sHtA + w * SHT_W;
    float* const sWB = sHtB + w * SHT_W;
    const int sm0 = r0 * 32 + ((s0 ^ r0) << 2);
    const int sm1 = r1 * 32 + ((s1 ^ r1) << 2);
    const size_t g0 = (size_t)r0 * HID + K0 + s0 * 4;
    const size_t g1 = (size_t)r1 * HID + K0 + s1 * 4;

    const size_t rowOffA = (size_t)(rbA + w) * HID + cb + j;
    const size_t rowOffB = (size_t)(rbB + w) * HID + cb + j;
    int* const flagsA = g_flags + q * FST;
    int* const flagsB = g_flags + (q + 8) * FST;

    float xhA = 0.0f, xhB = 0.0f;
    if (w < 8) {
        xhA = __ldcg(&g_buf[rowOffA]);
        xhB = __ldcg(&g_buf[rowOffB]);
    }

    float4 pA0, pA1, pB0, pB1;

    for (int s = 0; s < SEQ; ++s) {
        float pfA = 0.0f, pfB = 0.0f;
        if (w < 8 && s + 1 < SEQ) {
            pfA = __ldcg(&g_buf[(size_t)(s + 1) * BH + rowOffA]);
            pfB = __ldcg(&g_buf[(size_t)(s + 1) * BH + rowOffB]);
        }

        // ================= phase A =================
        {
            float va = xhA;
            if (s > 0) {
                *(float4*)&sWA[sm0] = pA0;
                *(float4*)&sWA[sm1] = pA1;
                __syncwarp();

                ull acc[BGR];
#pragma unroll
                for (int r = 0; r < BGR; ++r) acc[r] = 0;
#pragma unroll
                for (int t = 0; t < 8; ++t) {
#pragma unroll
                    for (int r = 0; r < BGR; ++r) {
                        ulonglong2 h2 = *(const ulonglong2*)
                            &sWA[r * 32 + ((t ^ r) << 2)];
                        acc[r] = fma2(h2.x, wp[2 * t],     acc[r]);
                        acc[r] = fma2(h2.y, wp[2 * t + 1], acc[r]);
                    }
                }

                while (ldacq(&flagsB[s - 1]) < NPROD) { }
                {
                    const float* hb = g_buf + (size_t)(s - 1) * BH
                                    + (size_t)rbB * HID;
                    pB0 = __ldcg((const float4*)(hb + g0));
                    pB1 = __ldcg((const float4*)(hb + g1));
                }

#pragma unroll
                for (int r = 0; r < BGR; ++r) {
                    float lo, hi;
                    upk(acc[r], lo, hi);
                    sRdA[(r * 16 + w) * NCR + j] = lo + hi;
                }
                __syncthreads();

                if (w < 8) {
                    float sum = 0.0f;
#pragma unroll
                    for (int ww = 0; ww < 16; ++ww)
                        sum += sRdA[(w * 16 + ww) * NCR + j];
                    va += sum;
                }
            }
            if (w < 8) {
                g_buf[(size_t)s * BH + rowOffA] = tanhf(va);
                __syncwarp();
                if (j == 0) red_release(&flagsA[s], 1);
            }
        }

        // ================= phase B =================
        {
            float vb = xhB;
            if (s > 0) {
                *(float4*)&sWB[sm0] = pB0;
                *(float4*)&sWB[sm1] = pB1;
                __syncwarp();

                ull acc[BGR];
#pragma unroll
                for (int r = 0; r < BGR; ++r) acc[r] = 0;
#pragma unroll
                for (int t = 0; t < 8; ++t) {
#pragma unroll
                    for (int r = 0; r < BGR; ++r) {
                        ulonglong2 h2 = *(const ulonglong2*)
                            &sWB[r * 32 + ((t ^ r) << 2)];
                        acc[r] = fma2(h2.x, wp[2 * t],     acc[r]);
                        acc[r] = fma2(h2.y, wp[2 * t + 1], acc[r]);
                    }
                }

                if (s + 1 < SEQ) {
                    while (ldacq(&flagsA[s]) < NPROD) { }
                    const float* hb = g_buf + (size_t)s * BH
                                    + (size_t)rbA * HID;
                    pA0 = __ldcg((const float4*)(hb + g0));
                    pA1 = __ldcg((const float4*)(hb + g1));
                }

#pragma unroll
                for (int r = 0; r < BGR; ++r) {
                    float lo, hi;
                    upk(acc[r], lo, hi);
                    sRdB[(r * 16 + w) * NCR + j] = lo + hi;
                }
                __syncthreads();

                if (w < 8) {
                    float sum = 0.0f;
#pragma unroll
                    for (int ww = 0; ww < 16; ++ww)
                        sum += sRdB[(w * 16 + ww) * NCR + j];
                    vb += sum;
                }
            } else {
                while (ldacq(&flagsA[0]) < NPROD) { }
                const float* hb = g_buf + (size_t)rbA * HID;
                pA0 = __ldcg((const float4*)(hb + g0));
                pA1 = __ldcg((const float4*)(hb + g1));
            }
            if (w < 8) {
                g_buf[(size_t)s * BH + rowOffB] = tanhf(vb);
                __syncwarp();
                if (j == 0) red_release(&flagsB[s], 1);
            }
        }

        xhA = pfA;
        xhB = pfB;
    }
}

// ---------------------------------------------------------------------------
// kernel_launch
// Inputs: x[512,128,256], W_xh[256,512], W_hh[512,512],
//         W_hy[512,128], b_h[512], b_y[128]  -> out[512,128,128] fp32
// ---------------------------------------------------------------------------
extern "C" void kernel_launch(void* const* d_in, const int* in_sizes, int n_in,
                              void* d_out, int out_size) {
    const float* x   = (const float*)d_in[0];
    const float* Wxh = (const float*)d_in[1];
    const float* Whh = (const float*)d_in[2];
    const float* Why = (const float*)d_in[3];
    const float* bh  = (const float*)d_in[4];
    const float* by  = (const float*)d_in[5];
    float* out = (float*)d_out;

    float* buf = nullptr;
    cudaGetSymbolAddress((void**)&buf, g_buf);

    cudaFuncSetAttribute(rnn_recur_kernel,
                         cudaFuncAttributeMaxDynamicSharedMemorySize,
                         REC_SMEM_BYTES);

    // 0) zero flags
    zero_flags_kernel<<<(NG * FST + 255) / 256, 256>>>();

    // 1) xh = x @ W_xh + b_h -> g_buf   (packed-FFMA2 GEMM)
    {
        dim3 grid(HID / 64, (SEQ * BATCH) / 128);
        sgemm_bias_kernel<128, 64, 16, 8, 4><<<grid, 256>>>(
            x, Wxh, bh, buf, SEQ * BATCH, HID, INDIM);
    }

    // 2) recurrence (R13-proven, unchanged)
    rnn_recur_kernel<<<128, 512, REC_SMEM_BYTES>>>(Whh);

    // 3) out = hs @ W_hy + b_y   (packed-FFMA2 GEMM)
    {
        dim3 grid(ODIM / 64, (SEQ * BATCH) / 128);
        sgemm_bias_kernel<128, 64, 16, 8, 4><<<grid, 256>>>(
            buf, Why, by, out, SEQ * BATCH, ODIM, HID);
    }
}